// round 11
// baseline (speedup 1.0000x reference)
#include <cuda_runtime.h>
#include <cuda_fp16.h>
#include <float.h>
#include <stdint.h>

// ---------------------------------------------------------------------------
// Problem constants
// ---------------------------------------------------------------------------
#define BATCH 16
#define CH    256
#define HH    32
#define WW    32
#define NTOK  (BATCH*HH*WW)           // 16384
#define KCODE 8192
#define QUANT_ELEMS (BATCH*CH*HH*WW)  // 4194304
#define LOSS_OFF  QUANT_ELEMS
#define IDX_OFF   (QUANT_ELEMS + 1)

#define M_TILE 128
#define N_TILE 128
#define N_TILES (KCODE / N_TILE)      // 64
#define KC 64
#define N_CHUNKS (CH / KC)            // 4
#define CHUNK_BYTES 16384             // 128 rows x 128B
#define STAGE_BYTES 16384
#define N_STAGES 6
#define TOTAL_ITERS (N_TILES * N_CHUNKS)  // 256

// 2*B, B = 12-sigma bound on 1-term fp16 v-score error (std ~6.3e-3)
#define WIN2B 0.15f

#define FBT 16
#define FB_SEGQ 4                     // 128-code segments per fb work item

// ---------------------------------------------------------------------------
// Device scratch (allocation-free)
// ---------------------------------------------------------------------------
__device__ __align__(128) uint8_t d_eblob[(size_t)TOTAL_ITERS * STAGE_BYTES]; // 4 MB
__device__ float  d_enorm[KCODE];
__device__ float  d_enorm05[KCODE];
__device__ int    d_idx[NTOK];
__device__ float  d_dist[NTOK];       // per-token score ||e||^2 - 2 x.e
__device__ int    d_ref_count;
__device__ int    d_ref_n[NTOK];
__device__ int    d_ref_i1[NTOK];
__device__ int    d_ref_i2[NTOK];
__device__ int    d_fb_count;
__device__ int    d_fb_list[NTOK];
__device__ unsigned long long d_fb_best[NTOK];
__device__ double d_loss_acc;         // Sum||x||^2 + Sum score

// ---------------------------------------------------------------------------
// Helpers
// ---------------------------------------------------------------------------
__device__ __forceinline__ uint32_t smem_u32(const void* p) {
    uint32_t a;
    asm("{ .reg .u64 t; cvta.to.shared.u64 t, %1; cvt.u32.u64 %0, t; }" : "=r"(a) : "l"(p));
    return a;
}
#define SWZ128(off) ((off) ^ (((off) >> 3) & 0x70))

__device__ __forceinline__ void ldsm4(uint32_t* r, uint32_t addr) {
    asm volatile("ldmatrix.sync.aligned.m8n8.x4.shared.b16 {%0,%1,%2,%3}, [%4];"
                 : "=r"(r[0]), "=r"(r[1]), "=r"(r[2]), "=r"(r[3]) : "r"(addr));
}

__device__ __forceinline__ void mma16816(float* d, const uint32_t* a,
                                         uint32_t b0, uint32_t b1) {
    asm volatile(
        "mma.sync.aligned.m16n8k16.row.col.f32.f16.f16.f32 "
        "{%0,%1,%2,%3}, {%4,%5,%6,%7}, {%8,%9}, {%0,%1,%2,%3};"
        : "+f"(d[0]), "+f"(d[1]), "+f"(d[2]), "+f"(d[3])
        : "r"(a[0]), "r"(a[1]), "r"(a[2]), "r"(a[3]), "r"(b0), "r"(b1));
}

__device__ __forceinline__ void cpasync16(uint32_t dst, const void* src) {
    asm volatile("cp.async.cg.shared.global [%0], [%1], 16;" :: "r"(dst), "l"(src));
}

__device__ __forceinline__ unsigned ord_f32(float f) {
    unsigned u = __float_as_uint(f);
    return (u & 0x80000000u) ? ~u : (u | 0x80000000u);
}
__device__ __forceinline__ float ord_inv(unsigned o) {
    unsigned bits = (o & 0x80000000u) ? (o ^ 0x80000000u) : ~o;
    return __uint_as_float(bits);
}

// top-3 insert; third slot value-only
__device__ __forceinline__ void ins3vi(float v, int i,
                                       float& v1, int& i1,
                                       float& v2, int& i2, float& v3) {
    if (v > v3) {
        if (v > v1)      { v3 = v2; v2 = v1; i2 = i1; v1 = v; i1 = i; }
        else if (v > v2) { v3 = v2; v2 = v;  i2 = i; }
        else             { v3 = v; }
    }
}

// ---------------------------------------------------------------------------
// Kernel A (fused): one warp per code: norm + fp16 convert + swizzled store.
// ---------------------------------------------------------------------------
__global__ void prep_eblob_kernel(const float* __restrict__ E) {
    if (blockIdx.x == 0 && threadIdx.x == 0) {
        d_loss_acc = 0.0; d_fb_count = 0; d_ref_count = 0;
    }
    const int k    = blockIdx.x * 8 + (threadIdx.x >> 5);
    const int lane = threadIdx.x & 31;
    const int d0   = lane * 8;
    const float* row = E + (size_t)k * CH + d0;
    float4 a = *(const float4*)row;
    float4 c = *(const float4*)(row + 4);

    float s = a.x*a.x + a.y*a.y + a.z*a.z + a.w*a.w
            + c.x*c.x + c.y*c.y + c.z*c.z + c.w*c.w;
    #pragma unroll
    for (int o = 16; o > 0; o >>= 1) s += __shfl_xor_sync(0xFFFFFFFFu, s, o);
    if (lane == 0) { d_enorm[k] = s; d_enorm05[k] = 0.5f * s; }

    __half h0[4], h1[4];
    h0[0] = __float2half_rn(a.x); h0[1] = __float2half_rn(a.y);
    h0[2] = __float2half_rn(a.z); h0[3] = __float2half_rn(a.w);
    h1[0] = __float2half_rn(c.x); h1[1] = __float2half_rn(c.y);
    h1[2] = __float2half_rn(c.z); h1[3] = __float2half_rn(c.w);

    int ct = k >> 7, rw = k & 127, kc = d0 >> 6, col = d0 & 63;
    size_t chunk = ((size_t)(ct * N_CHUNKS + kc)) * STAGE_BYTES;
    *(uint2*)(d_eblob + chunk + SWZ128((uint32_t)(rw * 128 + col * 2)))     = *(uint2*)h0;
    *(uint2*)(d_eblob + chunk + SWZ128((uint32_t)(rw * 128 + col * 2 + 8))) = *(uint2*)h1;
}

// ---------------------------------------------------------------------------
// Kernel C: 1-term fp16 GEMM, A register-resident, B np-half pipelined.
// SMEM: A stage [4x16KB]=64KB | B[6 x 16KB]=96KB -> 160KB dynamic
// ---------------------------------------------------------------------------
#define SM_A   0
#define SM_B   65536
#define SM_TOTAL 163840

__global__ __launch_bounds__(256, 1)
void vq_mma_kernel(const float* __restrict__ X) {
    extern __shared__ char smem[];
    __shared__ float x2p[256];
    const uint32_t sb = smem_u32(smem);
    const int tid  = threadIdx.x;
    const int lane = tid & 31;
    const int wid  = tid >> 5;
    const int warpM = wid >> 1;
    const int warpN = wid & 1;
    const int n0 = blockIdx.x * M_TILE;
    const int b  = n0 >> 10;
    const int r0 = n0 & 1023;
    const float* Xb = X + (size_t)b * (CH * HH * WW) + r0;

    auto copy_stage = [&](int it) {
        uint32_t dst = sb + SM_B + (uint32_t)(it % N_STAGES) * STAGE_BYTES + tid * 16u;
        const uint8_t* src = d_eblob + (size_t)it * STAGE_BYTES + tid * 16;
        #pragma unroll
        for (int p = 0; p < 4; p++) cpasync16(dst + p * 4096u, src + p * 4096);
        asm volatile("cp.async.commit_group;" ::: "memory");
    };
    copy_stage(0); copy_stage(1); copy_stage(2); copy_stage(3);

    // ---- A prologue: stage X (fp16, swizzled); accumulate exact Sum x^2 ----
    float x2 = 0.f;
    #pragma unroll
    for (int l = 0; l < M_TILE * CH / 256; l++) {
        int i = tid + l * 256;
        int d = i >> 7, m = i & 127;
        float v = Xb[(size_t)d * 1024 + m];
        x2 = fmaf(v, v, x2);
        int chunk = d >> 6, c = d & 63;
        uint32_t off = SWZ128((uint32_t)(m * 128 + c * 2));
        *(__half*)(smem + SM_A + chunk * CHUNK_BYTES + off) = __float2half_rn(v);
    }
    x2p[tid] = x2;
    __syncthreads();
    if (tid < 128) x2p[tid] += x2p[tid + 128];
    __syncthreads();
    if (tid < 64) x2p[tid] += x2p[tid + 64];
    __syncthreads();
    if (tid < 32) {
        float s = x2p[tid] + x2p[tid + 32];
        #pragma unroll
        for (int o = 16; o > 0; o >>= 1) s += __shfl_xor_sync(0xFFFFFFFFu, s, o);
        if (tid == 0) atomicAdd(&d_loss_acc, (double)s);
    }

    const uint32_t a_row = (uint32_t)(warpM * 32 + (lane & 15)) * 128;
    const uint32_t a_col = (uint32_t)(lane >> 4) * 16;
    const uint32_t b_row = (uint32_t)(warpN * 64 + (lane & 7) + ((lane >> 4) * 8)) * 128;
    const uint32_t b_col = (uint32_t)((lane >> 3) & 1) * 16;

    uint32_t Areg[N_CHUNKS][4][2][4];   // [kc][ks][mt][reg]
    #pragma unroll
    for (int kc = 0; kc < N_CHUNKS; kc++)
        #pragma unroll
        for (int ks = 0; ks < 4; ks++)
            #pragma unroll
            for (int mt = 0; mt < 2; mt++)
                ldsm4(Areg[kc][ks][mt],
                      sb + SM_A + (uint32_t)kc * CHUNK_BYTES +
                      SWZ128(a_row + (uint32_t)mt * 2048 + a_col + (uint32_t)ks * 32));

    float tv1[4], tv2[4], tv3[4]; int ti1[4], ti2[4];
    #pragma unroll
    for (int t = 0; t < 4; t++) {
        tv1[t] = tv2[t] = tv3[t] = -FLT_MAX;
        ti1[t] = ti2[t] = 0;
    }

    const float2* en2 = (const float2*)d_enorm05;

    for (int ct = 0; ct < N_TILES; ct++) {
        float acc[2][8][4];
        #pragma unroll
        for (int mt = 0; mt < 2; mt++)
            #pragma unroll
            for (int nt = 0; nt < 8; nt++)
                #pragma unroll
                for (int e = 0; e < 4; e++) acc[mt][nt][e] = 0.f;

        #pragma unroll
        for (int kc2 = 0; kc2 < N_CHUNKS; kc2 += 2) {
            int it = ct * N_CHUNKS + kc2;
            asm volatile("cp.async.wait_group 2;" ::: "memory");
            __syncthreads();
            if (it + 4 < TOTAL_ITERS) copy_stage(it + 4);
            if (it + 5 < TOTAL_ITERS) copy_stage(it + 5);

            #pragma unroll
            for (int kk = 0; kk < 2; kk++) {
                const int kc = kc2 + kk;
                const uint32_t bh_base =
                    sb + SM_B + (uint32_t)((it + kk) % N_STAGES) * STAGE_BYTES;

                // np-half pipelined: bfA = np{0,1}, bfB = np{2,3}
                uint32_t bfA[2][4], bfB[2][4];
                auto ldB = [&](int ks, int npb, uint32_t f[2][4]) {
                    const uint32_t kb = (uint32_t)ks * 32;
                    #pragma unroll
                    for (int j = 0; j < 2; j++)
                        ldsm4(f[j], bh_base +
                              SWZ128(b_row + (uint32_t)(npb + j) * 2048 + b_col + kb));
                };
                ldB(0, 0, bfA);
                #pragma unroll
                for (int ks = 0; ks < 4; ks++) {
                    ldB(ks, 2, bfB);
                    // first half: nt 0..3 (np 0,1) — overlaps bfB loads
                    #pragma unroll
                    for (int mt = 0; mt < 2; mt++)
                        #pragma unroll
                        for (int nt = 0; nt < 4; nt++)
                            mma16816(acc[mt][nt], Areg[kc][ks][mt],
                                     bfA[nt >> 1][(nt & 1) * 2],
                                     bfA[nt >> 1][(nt & 1) * 2 + 1]);
                    if (ks < 3) ldB(ks + 1, 0, bfA);
                    // second half: nt 4..7 (np 2,3) — overlaps next bfA loads
                    #pragma unroll
                    for (int mt = 0; mt < 2; mt++)
                        #pragma unroll
                        for (int nt = 4; nt < 8; nt++)
                            mma16816(acc[mt][nt], Areg[kc][ks][mt],
                                     bfB[(nt - 4) >> 1][(nt & 1) * 2],
                                     bfB[(nt - 4) >> 1][(nt & 1) * 2 + 1]);
                }
            }
        }

        const int cb = ct * N_TILE + warpN * 64;
        #pragma unroll
        for (int mt = 0; mt < 2; mt++)
            #pragma unroll
            for (int nt = 0; nt < 8; nt++) {
                int col0 = cb + nt * 8 + (lane & 3) * 2;
                float2 e = __ldg(en2 + (col0 >> 1));
                #pragma unroll
                for (int half = 0; half < 2; half++) {
                    int t = mt * 2 + half;
                    float v0 = acc[mt][nt][half * 2 + 0] - e.x;
                    float v1 = acc[mt][nt][half * 2 + 1] - e.y;
                    ins3vi(v0, col0,     tv1[t], ti1[t], tv2[t], ti2[t], tv3[t]);
                    ins3vi(v1, col0 + 1, tv1[t], ti1[t], tv2[t], ti2[t], tv3[t]);
                }
            }
    }

    #pragma unroll
    for (int t = 0; t < 4; t++) {
        #pragma unroll
        for (int m = 1; m <= 2; m <<= 1) {
            float ov1 = __shfl_xor_sync(0xFFFFFFFFu, tv1[t], m);
            float ov2 = __shfl_xor_sync(0xFFFFFFFFu, tv2[t], m);
            float ov3 = __shfl_xor_sync(0xFFFFFFFFu, tv3[t], m);
            int   oi1 = __shfl_xor_sync(0xFFFFFFFFu, ti1[t], m);
            int   oi2 = __shfl_xor_sync(0xFFFFFFFFu, ti2[t], m);
            ins3vi(ov1, oi1, tv1[t], ti1[t], tv2[t], ti2[t], tv3[t]);
            ins3vi(ov2, oi2, tv1[t], ti1[t], tv2[t], ti2[t], tv3[t]);
            if (ov3 > tv3[t]) tv3[t] = ov3;
        }
    }

    __syncthreads();
    float* rv1 = (float*)(smem + SM_B);
    float* rv2 = (float*)(smem + SM_B + 1024);
    float* rv3 = (float*)(smem + SM_B + 2048);
    int*   ri1 = (int*)  (smem + SM_B + 3072);
    int*   ri2 = (int*)  (smem + SM_B + 4096);
    #pragma unroll
    for (int t = 0; t < 4; t++) {
        if ((lane & 3) == 0) {
            int mt = t >> 1, half = t & 1;
            int tl = warpN * 128 + warpM * 32 + mt * 16 + half * 8 + (lane >> 2);
            rv1[tl] = tv1[t]; rv2[tl] = tv2[t]; rv3[tl] = tv3[t];
            ri1[tl] = ti1[t]; ri2[tl] = ti2[t];
        }
    }
    __syncthreads();
    if (tid < M_TILE) {
        float v1 = rv1[tid], v2 = rv2[tid], v3 = rv3[tid];
        int   i1 = ri1[tid], i2 = ri2[tid];
        ins3vi(rv1[128 + tid], ri1[128 + tid], v1, i1, v2, i2, v3);
        ins3vi(rv2[128 + tid], ri2[128 + tid], v1, i1, v2, i2, v3);
        if (rv3[128 + tid] > v3) v3 = rv3[128 + tid];
        int n = n0 + tid;
        d_idx[n]  = i1;
        d_dist[n] = -2.f * v1;
        if (v1 - v3 < WIN2B) {
            int p = atomicAdd(&d_fb_count, 1);
            if (p < NTOK) { d_fb_list[p] = n; d_fb_best[n] = 0xFFFFFFFFFFFFFFFFull; }
        } else if (v1 - v2 < WIN2B) {
            int p = atomicAdd(&d_ref_count, 1);
            if (p < NTOK) { d_ref_n[p] = n; d_ref_i1[p] = i1; d_ref_i2[p] = i2; }
        }
    }
}

// ---------------------------------------------------------------------------
// Kernel D1: exact fp32 refine of 2 candidate codes. One warp per token.
// ---------------------------------------------------------------------------
__global__ __launch_bounds__(256)
void refine_kernel(const float* __restrict__ X, const float* __restrict__ E) {
    const int lane = threadIdx.x & 31;
    const int gw = blockIdx.x * 8 + (threadIdx.x >> 5);
    int cnt = d_ref_count; if (cnt > NTOK) cnt = NTOK;
    for (int w = gw; w < cnt; w += gridDim.x * 8) {
        int n = d_ref_n[w], i1 = d_ref_i1[w], i2 = d_ref_i2[w];
        int b = n >> 10, r = n & 1023;
        const float* Xp = X + (size_t)b * (CH * HH * WW) + r;
        const float* e1 = E + (size_t)i1 * CH;
        const float* e2 = E + (size_t)i2 * CH;
        float s1 = 0.f, s2 = 0.f;
        #pragma unroll
        for (int j = 0; j < CH / 32; j++) {
            int d = lane + j * 32;
            float x = Xp[(size_t)d * 1024];
            s1 = fmaf(x, e1[d], s1);
            s2 = fmaf(x, e2[d], s2);
        }
        #pragma unroll
        for (int o = 16; o > 0; o >>= 1) {
            s1 += __shfl_xor_sync(0xFFFFFFFFu, s1, o);
            s2 += __shfl_xor_sync(0xFFFFFFFFu, s2, o);
        }
        if (lane == 0) {
            float sc1 = fmaf(-2.f, s1, d_enorm[i1]);
            float sc2 = fmaf(-2.f, s2, d_enorm[i2]);
            bool two = (sc2 < sc1 || (sc2 == sc1 && i2 < i1));
            d_idx[n]  = two ? i2 : i1;
            d_dist[n] = two ? sc2 : sc1;
        }
    }
}

// ---------------------------------------------------------------------------
// Kernel D2: full exact fp32 rescan (rare). Work item = (16-token group,
// 512-code quad-segment): X tile loaded ONCE per item, per-thread running min.
// ---------------------------------------------------------------------------
__global__ __launch_bounds__(128)
void fb_kernel(const float* __restrict__ X, const float* __restrict__ E) {
    __shared__ float xs[FBT][CH];
    __shared__ unsigned long long red[FBT][128];
    const int tid = threadIdx.x;
    int cnt = d_fb_count; if (cnt > NTOK) cnt = NTOK;
    const int ngrp = (cnt + FBT - 1) / FBT;
    const int items = ngrp * (KCODE / (128 * FB_SEGQ));   // ngrp * 16
    for (int w = blockIdx.x; w < items; w += gridDim.x) {
        const int grp = w >> 4, segq = w & 15;
        __syncthreads();
        for (int i = tid; i < FBT * CH; i += 128) {
            int t = i >> 8, d = i & 255;
            int li = grp * FBT + t;
            int n = d_fb_list[li < cnt ? li : 0];
            int b = n >> 10, r = n & 1023;
            xs[t][d] = X[(size_t)b * (CH * HH * WW) + (size_t)d * 1024 + r];
        }
        __syncthreads();

        unsigned long long best[FBT];
        #pragma unroll
        for (int t = 0; t < FBT; t++) best[t] = 0xFFFFFFFFFFFFFFFFull;

        #pragma unroll
        for (int q = 0; q < FB_SEGQ; q++) {
            const int c = (segq * FB_SEGQ + q) * 128 + tid;
            const float4* e4 = (const float4*)(E + (size_t)c * CH);
            float dots[FBT];
            #pragma unroll
            for (int t = 0; t < FBT; t++) dots[t] = 0.f;
            #pragma unroll 4
            for (int p = 0; p < CH / 4; p++) {
                float4 e = e4[p];
                #pragma unroll
                for (int t = 0; t < FBT; t++) {
                    float4 a = *(const float4*)&xs[t][p * 4];
                    dots[t] = fmaf(a.x, e.x, fmaf(a.y, e.y, fmaf(a.z, e.z, fmaf(a.w, e.w, dots[t]))));
                }
            }
            float en = d_enorm[c];
            #pragma unroll
            for (int t = 0; t < FBT; t++) {
                float sc = fmaf(-2.f, dots[t], en);
                unsigned long long key =
                    ((unsigned long long)ord_f32(sc) << 32) | (unsigned)c;
                if (key < best[t]) best[t] = key;
            }
        }
        #pragma unroll
        for (int t = 0; t < FBT; t++) red[t][tid] = best[t];
        __syncthreads();
        {
            int t = tid >> 3, l8 = tid & 7;
            unsigned long long m = 0xFFFFFFFFFFFFFFFFull;
            #pragma unroll
            for (int j = 0; j < 16; j++) {
                unsigned long long v = red[t][l8 + j * 8];
                if (v < m) m = v;
            }
            #pragma unroll
            for (int o = 4; o > 0; o >>= 1) {
                unsigned long long v = __shfl_xor_sync(0xFFFFFFFFu, m, o);
                if (v < m) m = v;
            }
            int li = grp * FBT + t;
            if (l8 == 0 && li < cnt) atomicMin(&d_fb_best[d_fb_list[li]], m);
        }
    }
}

__global__ void fb_finalize_kernel() {
    int w = blockIdx.x * 256 + threadIdx.x;
    int cnt = d_fb_count; if (cnt > NTOK) cnt = NTOK;
    if (w < cnt) {
        int n = d_fb_list[w];
        unsigned long long key = d_fb_best[n];
        d_idx[n]  = (int)(unsigned)(key & 0xFFFFFFFFull);
        d_dist[n] = ord_inv((unsigned)(key >> 32));
    }
}

// ---------------------------------------------------------------------------
// Kernel E: pure gather (coalesced via smem staging) + score-sum. 32 tok/block.
// ---------------------------------------------------------------------------
__global__ __launch_bounds__(256)
void gather_kernel(const float* __restrict__ E, float* __restrict__ out) {
    __shared__ float es[32][257];
    const int tid = threadIdx.x;
    const int n0 = blockIdx.x * 32;
    const int b  = n0 >> 10;
    const int r0 = n0 & 1023;

    #pragma unroll 4
    for (int p = 0; p < 32; p++) {
        int k = d_idx[n0 + p];
        es[p][tid] = E[(size_t)k * CH + tid];
    }
    if (tid < 32) {
        out[IDX_OFF + n0 + tid] = (float)d_idx[n0 + tid];
        float s = d_dist[n0 + tid];
        #pragma unroll
        for (int o = 16; o > 0; o >>= 1) s += __shfl_xor_sync(0xFFFFFFFFu, s, o);
        if (tid == 0) atomicAdd(&d_loss_acc, (double)s);
    }
    __syncthreads();

    const int t = tid & 31;
    const int cg = tid >> 5;
    #pragma unroll 8
    for (int p = 0; p < 32; p++) {
        int c = cg + p * 8;
        out[(size_t)b * (CH * HH * WW) + (size_t)c * 1024 + r0 + t] = es[t][c];
    }
}

__global__ void finalize_kernel(float* __restrict__ out) {
    out[LOSS_OFF] = (float)(d_loss_acc * 1.25 / (double)QUANT_ELEMS);
}

// ---------------------------------------------------------------------------
extern "C" void kernel_launch(void* const* d_in, const int* in_sizes, int n_in,
                              void* d_out, int out_size) {
    const float* X = (const float*)d_in[0];
    const float* E = (const float*)d_in[1];
    float* out = (float*)d_out;

    cudaFuncSetAttribute(vq_mma_kernel, cudaFuncAttributeMaxDynamicSharedMemorySize, SM_TOTAL);

    prep_eblob_kernel<<<KCODE / 8, 256>>>(E);
    vq_mma_kernel<<<NTOK / M_TILE, 256, SM_TOTAL>>>(X);
    refine_kernel<<<128, 256>>>(X, E);
    fb_kernel<<<256, 128>>>(X, E);
    fb_finalize_kernel<<<NTOK / 256, 256>>>();
    gather_kernel<<<NTOK / 32, 256>>>(E, out);
    finalize_kernel<<<1, 1>>>(out);
}

// round 13
// speedup vs baseline: 1.0944x; 1.0944x over previous
#include <cuda_runtime.h>
#include <cuda_fp16.h>
#include <float.h>
#include <stdint.h>

// ---------------------------------------------------------------------------
// Problem constants
// ---------------------------------------------------------------------------
#define BATCH 16
#define CH    256
#define HH    32
#define WW    32
#define NTOK  (BATCH*HH*WW)           // 16384
#define KCODE 8192
#define QUANT_ELEMS (BATCH*CH*HH*WW)  // 4194304
#define LOSS_OFF  QUANT_ELEMS
#define IDX_OFF   (QUANT_ELEMS + 1)

#define M_TILE 128
#define N_TILE 128
#define N_TILES (KCODE / N_TILE)      // 64
#define KC 64
#define N_CHUNKS (CH / KC)            // 4
#define CHUNK_BYTES 16384             // 128 rows x 128B
#define STAGE_BYTES 16384
#define N_STAGES 6
#define TOTAL_ITERS (N_TILES * N_CHUNKS)  // 256

// 2*B, B = 12-sigma bound on 1-term fp16 v-score error (std ~6.3e-3)
#define WIN2B 0.15f

#define FBT 16

// ---------------------------------------------------------------------------
// Device scratch (allocation-free)
// ---------------------------------------------------------------------------
__device__ __align__(128) uint8_t d_eblob[(size_t)TOTAL_ITERS * STAGE_BYTES]; // 4 MB
__device__ float  d_enorm[KCODE];
__device__ float  d_enorm05[KCODE];
__device__ int    d_idx[NTOK];
__device__ float  d_dist[NTOK];       // per-token score ||e||^2 - 2 x.e
__device__ int    d_ref_count;
__device__ int    d_ref_n[NTOK];
__device__ int    d_ref_i1[NTOK];
__device__ int    d_ref_i2[NTOK];
__device__ int    d_fb_count;
__device__ int    d_fb_list[NTOK];
__device__ unsigned long long d_fb_best[NTOK];
__device__ double d_loss_acc;         // Sum||x||^2 + Sum score

// ---------------------------------------------------------------------------
// Helpers
// ---------------------------------------------------------------------------
__device__ __forceinline__ uint32_t smem_u32(const void* p) {
    uint32_t a;
    asm("{ .reg .u64 t; cvta.to.shared.u64 t, %1; cvt.u32.u64 %0, t; }" : "=r"(a) : "l"(p));
    return a;
}
#define SWZ128(off) ((off) ^ (((off) >> 3) & 0x70))

__device__ __forceinline__ void ldsm4(uint32_t* r, uint32_t addr) {
    asm volatile("ldmatrix.sync.aligned.m8n8.x4.shared.b16 {%0,%1,%2,%3}, [%4];"
                 : "=r"(r[0]), "=r"(r[1]), "=r"(r[2]), "=r"(r[3]) : "r"(addr));
}

__device__ __forceinline__ void mma16816(float* d, const uint32_t* a,
                                         uint32_t b0, uint32_t b1) {
    asm volatile(
        "mma.sync.aligned.m16n8k16.row.col.f32.f16.f16.f32 "
        "{%0,%1,%2,%3}, {%4,%5,%6,%7}, {%8,%9}, {%0,%1,%2,%3};"
        : "+f"(d[0]), "+f"(d[1]), "+f"(d[2]), "+f"(d[3])
        : "r"(a[0]), "r"(a[1]), "r"(a[2]), "r"(a[3]), "r"(b0), "r"(b1));
}

__device__ __forceinline__ void cpasync16(uint32_t dst, const void* src) {
    asm volatile("cp.async.cg.shared.global [%0], [%1], 16;" :: "r"(dst), "l"(src));
}

__device__ __forceinline__ unsigned ord_f32(float f) {
    unsigned u = __float_as_uint(f);
    return (u & 0x80000000u) ? ~u : (u | 0x80000000u);
}
__device__ __forceinline__ float ord_inv(unsigned o) {
    unsigned bits = (o & 0x80000000u) ? (o ^ 0x80000000u) : ~o;
    return __uint_as_float(bits);
}

// top-3 insert; third slot value-only
__device__ __forceinline__ void ins3vi(float v, int i,
                                       float& v1, int& i1,
                                       float& v2, int& i2, float& v3) {
    if (v > v3) {
        if (v > v1)      { v3 = v2; v2 = v1; i2 = i1; v1 = v; i1 = i; }
        else if (v > v2) { v3 = v2; v2 = v;  i2 = i; }
        else             { v3 = v; }
    }
}

// ---------------------------------------------------------------------------
// Kernel A (fused): one warp per code: norm + fp16 convert + swizzled store.
// ---------------------------------------------------------------------------
__global__ void prep_eblob_kernel(const float* __restrict__ E) {
    if (blockIdx.x == 0 && threadIdx.x == 0) {
        d_loss_acc = 0.0; d_fb_count = 0; d_ref_count = 0;
    }
    const int k    = blockIdx.x * 8 + (threadIdx.x >> 5);
    const int lane = threadIdx.x & 31;
    const int d0   = lane * 8;
    const float* row = E + (size_t)k * CH + d0;
    float4 a = *(const float4*)row;
    float4 c = *(const float4*)(row + 4);

    float s = a.x*a.x + a.y*a.y + a.z*a.z + a.w*a.w
            + c.x*c.x + c.y*c.y + c.z*c.z + c.w*c.w;
    #pragma unroll
    for (int o = 16; o > 0; o >>= 1) s += __shfl_xor_sync(0xFFFFFFFFu, s, o);
    if (lane == 0) { d_enorm[k] = s; d_enorm05[k] = 0.5f * s; }

    __half h0[4], h1[4];
    h0[0] = __float2half_rn(a.x); h0[1] = __float2half_rn(a.y);
    h0[2] = __float2half_rn(a.z); h0[3] = __float2half_rn(a.w);
    h1[0] = __float2half_rn(c.x); h1[1] = __float2half_rn(c.y);
    h1[2] = __float2half_rn(c.z); h1[3] = __float2half_rn(c.w);

    int ct = k >> 7, rw = k & 127, kc = d0 >> 6, col = d0 & 63;
    size_t chunk = ((size_t)(ct * N_CHUNKS + kc)) * STAGE_BYTES;
    *(uint2*)(d_eblob + chunk + SWZ128((uint32_t)(rw * 128 + col * 2)))     = *(uint2*)h0;
    *(uint2*)(d_eblob + chunk + SWZ128((uint32_t)(rw * 128 + col * 2 + 8))) = *(uint2*)h1;
}

// ---------------------------------------------------------------------------
// Kernel C: 1-term fp16 GEMM, A register-resident, B np-half pipelined.
// SMEM: A stage [4x16KB]=64KB | B[6 x 16KB]=96KB -> 160KB dynamic
// ---------------------------------------------------------------------------
#define SM_A   0
#define SM_B   65536
#define SM_TOTAL 163840

__global__ __launch_bounds__(256, 1)
void vq_mma_kernel(const float* __restrict__ X) {
    extern __shared__ char smem[];
    __shared__ float x2p[256];
    const uint32_t sb = smem_u32(smem);
    const int tid  = threadIdx.x;
    const int lane = tid & 31;
    const int wid  = tid >> 5;
    const int warpM = wid >> 1;
    const int warpN = wid & 1;
    const int n0 = blockIdx.x * M_TILE;
    const int b  = n0 >> 10;
    const int r0 = n0 & 1023;
    const float* Xb = X + (size_t)b * (CH * HH * WW) + r0;

    auto copy_stage = [&](int it) {
        uint32_t dst = sb + SM_B + (uint32_t)(it % N_STAGES) * STAGE_BYTES + tid * 16u;
        const uint8_t* src = d_eblob + (size_t)it * STAGE_BYTES + tid * 16;
        #pragma unroll
        for (int p = 0; p < 4; p++) cpasync16(dst + p * 4096u, src + p * 4096);
        asm volatile("cp.async.commit_group;" ::: "memory");
    };
    copy_stage(0); copy_stage(1); copy_stage(2); copy_stage(3);

    // ---- A prologue: stage X (fp16, swizzled); accumulate exact Sum x^2 ----
    float x2 = 0.f;
    #pragma unroll
    for (int l = 0; l < M_TILE * CH / 256; l++) {
        int i = tid + l * 256;
        int d = i >> 7, m = i & 127;
        float v = Xb[(size_t)d * 1024 + m];
        x2 = fmaf(v, v, x2);
        int chunk = d >> 6, c = d & 63;
        uint32_t off = SWZ128((uint32_t)(m * 128 + c * 2));
        *(__half*)(smem + SM_A + chunk * CHUNK_BYTES + off) = __float2half_rn(v);
    }
    x2p[tid] = x2;
    __syncthreads();
    if (tid < 128) x2p[tid] += x2p[tid + 128];
    __syncthreads();
    if (tid < 64) x2p[tid] += x2p[tid + 64];
    __syncthreads();
    if (tid < 32) {
        float s = x2p[tid] + x2p[tid + 32];
        #pragma unroll
        for (int o = 16; o > 0; o >>= 1) s += __shfl_xor_sync(0xFFFFFFFFu, s, o);
        if (tid == 0) atomicAdd(&d_loss_acc, (double)s);
    }

    const uint32_t a_row = (uint32_t)(warpM * 32 + (lane & 15)) * 128;
    const uint32_t a_col = (uint32_t)(lane >> 4) * 16;
    const uint32_t b_row = (uint32_t)(warpN * 64 + (lane & 7) + ((lane >> 4) * 8)) * 128;
    const uint32_t b_col = (uint32_t)((lane >> 3) & 1) * 16;

    uint32_t Areg[N_CHUNKS][4][2][4];   // [kc][ks][mt][reg]
    #pragma unroll
    for (int kc = 0; kc < N_CHUNKS; kc++)
        #pragma unroll
        for (int ks = 0; ks < 4; ks++)
            #pragma unroll
            for (int mt = 0; mt < 2; mt++)
                ldsm4(Areg[kc][ks][mt],
                      sb + SM_A + (uint32_t)kc * CHUNK_BYTES +
                      SWZ128(a_row + (uint32_t)mt * 2048 + a_col + (uint32_t)ks * 32));

    float tv1[4], tv2[4], tv3[4]; int ti1[4], ti2[4];
    #pragma unroll
    for (int t = 0; t < 4; t++) {
        tv1[t] = tv2[t] = tv3[t] = -FLT_MAX;
        ti1[t] = ti2[t] = 0;
    }

    const float2* en2 = (const float2*)d_enorm05;

    for (int ct = 0; ct < N_TILES; ct++) {
        float acc[2][8][4];
        #pragma unroll
        for (int mt = 0; mt < 2; mt++)
            #pragma unroll
            for (int nt = 0; nt < 8; nt++)
                #pragma unroll
                for (int e = 0; e < 4; e++) acc[mt][nt][e] = 0.f;

        #pragma unroll
        for (int kc2 = 0; kc2 < N_CHUNKS; kc2 += 2) {
            int it = ct * N_CHUNKS + kc2;
            asm volatile("cp.async.wait_group 2;" ::: "memory");
            __syncthreads();
            if (it + 4 < TOTAL_ITERS) copy_stage(it + 4);
            if (it + 5 < TOTAL_ITERS) copy_stage(it + 5);

            #pragma unroll
            for (int kk = 0; kk < 2; kk++) {
                const int kc = kc2 + kk;
                const uint32_t bh_base =
                    sb + SM_B + (uint32_t)((it + kk) % N_STAGES) * STAGE_BYTES;

                // np-half pipelined: bfA = np{0,1}, bfB = np{2,3}
                uint32_t bfA[2][4], bfB[2][4];
                auto ldB = [&](int ks, int npb, uint32_t f[2][4]) {
                    const uint32_t kb = (uint32_t)ks * 32;
                    #pragma unroll
                    for (int j = 0; j < 2; j++)
                        ldsm4(f[j], bh_base +
                              SWZ128(b_row + (uint32_t)(npb + j) * 2048 + b_col + kb));
                };
                ldB(0, 0, bfA);
                #pragma unroll
                for (int ks = 0; ks < 4; ks++) {
                    ldB(ks, 2, bfB);
                    // first half: nt 0..3 (np 0,1) — overlaps bfB loads
                    #pragma unroll
                    for (int mt = 0; mt < 2; mt++)
                        #pragma unroll
                        for (int nt = 0; nt < 4; nt++)
                            mma16816(acc[mt][nt], Areg[kc][ks][mt],
                                     bfA[nt >> 1][(nt & 1) * 2],
                                     bfA[nt >> 1][(nt & 1) * 2 + 1]);
                    if (ks < 3) ldB(ks + 1, 0, bfA);
                    // second half: nt 4..7 (np 2,3) — overlaps next bfA loads
                    #pragma unroll
                    for (int mt = 0; mt < 2; mt++)
                        #pragma unroll
                        for (int nt = 4; nt < 8; nt++)
                            mma16816(acc[mt][nt], Areg[kc][ks][mt],
                                     bfB[(nt - 4) >> 1][(nt & 1) * 2],
                                     bfB[(nt - 4) >> 1][(nt & 1) * 2 + 1]);
                }
            }
        }

        const int cb = ct * N_TILE + warpN * 64;
        #pragma unroll
        for (int mt = 0; mt < 2; mt++)
            #pragma unroll
            for (int nt = 0; nt < 8; nt++) {
                int col0 = cb + nt * 8 + (lane & 3) * 2;
                float2 e = __ldg(en2 + (col0 >> 1));
                #pragma unroll
                for (int half = 0; half < 2; half++) {
                    int t = mt * 2 + half;
                    float v0 = acc[mt][nt][half * 2 + 0] - e.x;
                    float v1 = acc[mt][nt][half * 2 + 1] - e.y;
                    ins3vi(v0, col0,     tv1[t], ti1[t], tv2[t], ti2[t], tv3[t]);
                    ins3vi(v1, col0 + 1, tv1[t], ti1[t], tv2[t], ti2[t], tv3[t]);
                }
            }
    }

    #pragma unroll
    for (int t = 0; t < 4; t++) {
        #pragma unroll
        for (int m = 1; m <= 2; m <<= 1) {
            float ov1 = __shfl_xor_sync(0xFFFFFFFFu, tv1[t], m);
            float ov2 = __shfl_xor_sync(0xFFFFFFFFu, tv2[t], m);
            float ov3 = __shfl_xor_sync(0xFFFFFFFFu, tv3[t], m);
            int   oi1 = __shfl_xor_sync(0xFFFFFFFFu, ti1[t], m);
            int   oi2 = __shfl_xor_sync(0xFFFFFFFFu, ti2[t], m);
            ins3vi(ov1, oi1, tv1[t], ti1[t], tv2[t], ti2[t], tv3[t]);
            ins3vi(ov2, oi2, tv1[t], ti1[t], tv2[t], ti2[t], tv3[t]);
            if (ov3 > tv3[t]) tv3[t] = ov3;
        }
    }

    __syncthreads();
    float* rv1 = (float*)(smem + SM_B);
    float* rv2 = (float*)(smem + SM_B + 1024);
    float* rv3 = (float*)(smem + SM_B + 2048);
    int*   ri1 = (int*)  (smem + SM_B + 3072);
    int*   ri2 = (int*)  (smem + SM_B + 4096);
    #pragma unroll
    for (int t = 0; t < 4; t++) {
        if ((lane & 3) == 0) {
            int mt = t >> 1, half = t & 1;
            int tl = warpN * 128 + warpM * 32 + mt * 16 + half * 8 + (lane >> 2);
            rv1[tl] = tv1[t]; rv2[tl] = tv2[t]; rv3[tl] = tv3[t];
            ri1[tl] = ti1[t]; ri2[tl] = ti2[t];
        }
    }
    __syncthreads();
    if (tid < M_TILE) {
        float v1 = rv1[tid], v2 = rv2[tid], v3 = rv3[tid];
        int   i1 = ri1[tid], i2 = ri2[tid];
        ins3vi(rv1[128 + tid], ri1[128 + tid], v1, i1, v2, i2, v3);
        ins3vi(rv2[128 + tid], ri2[128 + tid], v1, i1, v2, i2, v3);
        if (rv3[128 + tid] > v3) v3 = rv3[128 + tid];
        int n = n0 + tid;
        d_idx[n]  = i1;
        d_dist[n] = -2.f * v1;
        if (v1 - v3 < WIN2B) {
            int p = atomicAdd(&d_fb_count, 1);
            if (p < NTOK) { d_fb_list[p] = n; d_fb_best[n] = 0xFFFFFFFFFFFFFFFFull; }
        } else if (v1 - v2 < WIN2B) {
            int p = atomicAdd(&d_ref_count, 1);
            if (p < NTOK) { d_ref_n[p] = n; d_ref_i1[p] = i1; d_ref_i2[p] = i2; }
        }
    }
}

// ---------------------------------------------------------------------------
// Kernel D1: exact fp32 refine of 2 candidate codes. One warp per token.
// ---------------------------------------------------------------------------
__global__ __launch_bounds__(256)
void refine_kernel(const float* __restrict__ X, const float* __restrict__ E) {
    const int lane = threadIdx.x & 31;
    const int gw = blockIdx.x * 8 + (threadIdx.x >> 5);
    int cnt = d_ref_count; if (cnt > NTOK) cnt = NTOK;
    for (int w = gw; w < cnt; w += gridDim.x * 8) {
        int n = d_ref_n[w], i1 = d_ref_i1[w], i2 = d_ref_i2[w];
        int b = n >> 10, r = n & 1023;
        const float* Xp = X + (size_t)b * (CH * HH * WW) + r;
        const float* e1 = E + (size_t)i1 * CH;
        const float* e2 = E + (size_t)i2 * CH;
        float s1 = 0.f, s2 = 0.f;
        #pragma unroll
        for (int j = 0; j < CH / 32; j++) {
            int d = lane + j * 32;
            float x = Xp[(size_t)d * 1024];
            s1 = fmaf(x, e1[d], s1);
            s2 = fmaf(x, e2[d], s2);
        }
        #pragma unroll
        for (int o = 16; o > 0; o >>= 1) {
            s1 += __shfl_xor_sync(0xFFFFFFFFu, s1, o);
            s2 += __shfl_xor_sync(0xFFFFFFFFu, s2, o);
        }
        if (lane == 0) {
            float sc1 = fmaf(-2.f, s1, d_enorm[i1]);
            float sc2 = fmaf(-2.f, s2, d_enorm[i2]);
            bool two = (sc2 < sc1 || (sc2 == sc1 && i2 < i1));
            d_idx[n]  = two ? i2 : i1;
            d_dist[n] = two ? sc2 : sc1;
        }
    }
}

// ---------------------------------------------------------------------------
// Kernel D2: full exact fp32 rescan (rare), mini-GEMM tiles (round-10 form),
// spread wide: work item = (16-token group, 128-code segment).
// ---------------------------------------------------------------------------
__global__ __launch_bounds__(128)
void fb_kernel(const float* __restrict__ X, const float* __restrict__ E) {
    __shared__ float xs[FBT][CH];
    __shared__ unsigned long long red[FBT][128];
    const int tid = threadIdx.x;
    int cnt = d_fb_count; if (cnt > NTOK) cnt = NTOK;
    const int ngrp = (cnt + FBT - 1) / FBT;
    const int items = ngrp * (KCODE / 128);
    for (int w = blockIdx.x; w < items; w += gridDim.x) {
        const int grp = w >> 6, seg = w & 63;
        __syncthreads();
        for (int i = tid; i < FBT * CH; i += 128) {
            int t = i >> 8, d = i & 255;
            int li = grp * FBT + t;
            int n = d_fb_list[li < cnt ? li : 0];
            int b = n >> 10, r = n & 1023;
            xs[t][d] = X[(size_t)b * (CH * HH * WW) + (size_t)d * 1024 + r];
        }
        __syncthreads();
        const int c = seg * 128 + tid;
        const float4* e4 = (const float4*)(E + (size_t)c * CH);
        float dots[FBT];
        #pragma unroll
        for (int t = 0; t < FBT; t++) dots[t] = 0.f;
        #pragma unroll 4
        for (int q = 0; q < CH / 4; q++) {
            float4 e = e4[q];
            #pragma unroll
            for (int t = 0; t < FBT; t++) {
                float4 a = *(const float4*)&xs[t][q * 4];
                dots[t] = fmaf(a.x, e.x, fmaf(a.y, e.y, fmaf(a.z, e.z, fmaf(a.w, e.w, dots[t]))));
            }
        }
        float en = d_enorm[c];
        #pragma unroll
        for (int t = 0; t < FBT; t++) {
            float sc = fmaf(-2.f, dots[t], en);
            red[t][tid] = ((unsigned long long)ord_f32(sc) << 32) | (unsigned)c;
        }
        __syncthreads();
        {
            int t = tid >> 3, l8 = tid & 7;
            unsigned long long m = 0xFFFFFFFFFFFFFFFFull;
            #pragma unroll
            for (int j = 0; j < 16; j++) {
                unsigned long long v = red[t][l8 + j * 8];
                if (v < m) m = v;
            }
            #pragma unroll
            for (int o = 4; o > 0; o >>= 1) {
                unsigned long long v = __shfl_xor_sync(0xFFFFFFFFu, m, o);
                if (v < m) m = v;
            }
            int li = grp * FBT + t;
            if (l8 == 0 && li < cnt) atomicMin(&d_fb_best[d_fb_list[li]], m);
        }
    }
}

__global__ void fb_finalize_kernel() {
    int w = blockIdx.x * 256 + threadIdx.x;
    int cnt = d_fb_count; if (cnt > NTOK) cnt = NTOK;
    if (w < cnt) {
        int n = d_fb_list[w];
        unsigned long long key = d_fb_best[n];
        d_idx[n]  = (int)(unsigned)(key & 0xFFFFFFFFull);
        d_dist[n] = ord_inv((unsigned)(key >> 32));
    }
}

// ---------------------------------------------------------------------------
// Kernel E: pure gather (coalesced via smem staging) + score-sum. 32 tok/block.
// ---------------------------------------------------------------------------
__global__ __launch_bounds__(256)
void gather_kernel(const float* __restrict__ E, float* __restrict__ out) {
    __shared__ float es[32][257];
    const int tid = threadIdx.x;
    const int n0 = blockIdx.x * 32;
    const int b  = n0 >> 10;
    const int r0 = n0 & 1023;

    #pragma unroll 4
    for (int p = 0; p < 32; p++) {
        int k = d_idx[n0 + p];
        es[p][tid] = E[(size_t)k * CH + tid];
    }
    if (tid < 32) {
        out[IDX_OFF + n0 + tid] = (float)d_idx[n0 + tid];
        float s = d_dist[n0 + tid];
        #pragma unroll
        for (int o = 16; o > 0; o >>= 1) s += __shfl_xor_sync(0xFFFFFFFFu, s, o);
        if (tid == 0) atomicAdd(&d_loss_acc, (double)s);
    }
    __syncthreads();

    const int t = tid & 31;
    const int cg = tid >> 5;
    #pragma unroll 8
    for (int p = 0; p < 32; p++) {
        int c = cg + p * 8;
        out[(size_t)b * (CH * HH * WW) + (size_t)c * 1024 + r0 + t] = es[t][c];
    }
}

__global__ void finalize_kernel(float* __restrict__ out) {
    out[LOSS_OFF] = (float)(d_loss_acc * 1.25 / (double)QUANT_ELEMS);
}

// ---------------------------------------------------------------------------
extern "C" void kernel_launch(void* const* d_in, const int* in_sizes, int n_in,
                              void* d_out, int out_size) {
    const float* X = (const float*)d_in[0];
    const float* E = (const float*)d_in[1];
    float* out = (float*)d_out;

    cudaFuncSetAttribute(vq_mma_kernel, cudaFuncAttributeMaxDynamicSharedMemorySize, SM_TOTAL);

    prep_eblob_kernel<<<KCODE / 8, 256>>>(E);
    vq_mma_kernel<<<NTOK / M_TILE, 256, SM_TOTAL>>>(X);
    refine_kernel<<<128, 256>>>(X, E);
    fb_kernel<<<1024, 128>>>(X, E);
    fb_finalize_kernel<<<NTOK / 256, 256>>>();
    gather_kernel<<<NTOK / 32, 256>>>(E, out);
    finalize_kernel<<<1, 1>>>(out);
}